// round 6
// baseline (speedup 1.0000x reference)
#include <cuda_runtime.h>
#include <cuda_bf16.h>
#include <cstdint>
#include <math.h>

// Problem constants
#define B_  64
#define T_  1024
#define I_  128
#define H_  256
#define NT  (B_ * T_)          // 65536 rows
// recurrent-weight rows cached in shared memory (out of H_), must be even
#define CK  104

typedef unsigned long long u64;

// ---------------------------------------------------------------------------
// Static device scratch (no runtime allocation allowed)
// ---------------------------------------------------------------------------
__device__ float2 g_Z[(size_t)NT * H_];        // {zf, zc} x-part (+bias), 128 MB
__device__ float  g_y1[(size_t)NT * H_];       // layer-1 outputs, 64 MB
__device__ u64    g_Wh[2][H_ * H_];            // recurrent weights {wf,wc} packed, k-major

// ---------------------------------------------------------------------------
// f32x2 helpers (packed 2xfp32 FMA: full-rate FMA pipe on sm_103a)
// ---------------------------------------------------------------------------
__device__ __forceinline__ u64 pack2(float x, float y) {
    u64 r;
    asm("mov.b64 %0, {%1, %2};" : "=l"(r) : "f"(x), "f"(y));
    return r;
}
__device__ __forceinline__ void unpack2(u64 v, float& x, float& y) {
    asm("mov.b64 {%0, %1}, %2;" : "=f"(x), "=f"(y) : "l"(v));
}
__device__ __forceinline__ void ffma2(u64& d, u64 a, u64 b) {
    asm("fma.rn.f32x2 %0, %1, %2, %0;" : "+l"(d) : "l"(a), "l"(b));
}

// ---------------------------------------------------------------------------
// Repack recurrent weight rows: g_Wh[layer][k*H + j] = pack{Wf[D+k][j], Wc[D+k][j]}
// ---------------------------------------------------------------------------
__global__ void repack_wh(const float* __restrict__ Wf, const float* __restrict__ Wc,
                          int D, int layer)
{
    int j = threadIdx.x;
    int k = blockIdx.x;
    float wf = Wf[(size_t)(D + k) * H_ + j];
    float wc = Wc[(size_t)(D + k) * H_ + j];
    g_Wh[layer][k * H_ + j] = pack2(wf, wc);
}

// ---------------------------------------------------------------------------
// Precompute x-part of both gates:
//   g_Z[n][j] = { bf[j] + sum_d X[n][d]*Wf[d][j],  bc[j] + sum_d X[n][d]*Wc[d][j] }
// Tile: 128 rows x 32 cols per block, 256 threads, thread = 8 rows x 2 cols.
// ---------------------------------------------------------------------------
__global__ void __launch_bounds__(256) gemm_x(
    const float* __restrict__ Xext, int D, int useY1,
    const float* __restrict__ Wf, const float* __restrict__ Wc,
    const float* __restrict__ bf, const float* __restrict__ bc)
{
    const float* __restrict__ X = useY1 ? (const float*)g_y1 : Xext;

    __shared__ float2 Xs[16][130];   // x splatted {x,x}; row padded to 130 (16B-aligned)
    __shared__ float2 Ws[16][34];    // {wf,wc};       row padded to 34  (16B-aligned)

    const int tid = threadIdx.x;
    const int tx  = tid & 15;        // column-pair index
    const int ty  = tid >> 4;        // row group of 8
    const int n0  = blockIdx.x * 128;
    const int j0  = blockIdx.y * 32;
    const int jj  = j0 + 2 * tx;     // global column (even)

    u64 acc[8][2];
    {
        u64 bi0 = pack2(bf[jj],     bc[jj]);
        u64 bi1 = pack2(bf[jj + 1], bc[jj + 1]);
#pragma unroll
        for (int r = 0; r < 8; r++) { acc[r][0] = bi0; acc[r][1] = bi1; }
    }

    for (int d0 = 0; d0 < D; d0 += 16) {
        __syncthreads();
        // X tile: 128 rows x 16 cols, 2 float4 loads per thread, splat on store
        {
            int r  = tid >> 2;           // 0..63
            int c4 = (tid & 3) * 4;      // 0,4,8,12
#pragma unroll
            for (int rr = 0; rr < 2; rr++) {
                int row = r + rr * 64;
                float4 v = *(const float4*)&X[(size_t)(n0 + row) * D + d0 + c4];
                Xs[c4 + 0][row] = make_float2(v.x, v.x);
                Xs[c4 + 1][row] = make_float2(v.y, v.y);
                Xs[c4 + 2][row] = make_float2(v.z, v.z);
                Xs[c4 + 3][row] = make_float2(v.w, v.w);
            }
        }
        // W tile: 16 k x 32 j, interleave gates
        for (int e = tid; e < 512; e += 256) {
            int k = e >> 5, jw = e & 31;
            Ws[k][jw] = make_float2(Wf[(size_t)(d0 + k) * H_ + j0 + jw],
                                    Wc[(size_t)(d0 + k) * H_ + j0 + jw]);
        }
        __syncthreads();

#pragma unroll
        for (int kk = 0; kk < 16; kk++) {
            ulonglong2 wq = *(const ulonglong2*)&Ws[kk][2 * tx];     // w0, w1
            const ulonglong2* xp = (const ulonglong2*)&Xs[kk][ty * 8];
#pragma unroll
            for (int q = 0; q < 4; q++) {
                ulonglong2 xq = xp[q];                               // rows 2q, 2q+1
                ffma2(acc[2 * q + 0][0], xq.x, wq.x);
                ffma2(acc[2 * q + 0][1], xq.x, wq.y);
                ffma2(acc[2 * q + 1][0], xq.y, wq.x);
                ffma2(acc[2 * q + 1][1], xq.y, wq.y);
            }
        }
    }

#pragma unroll
    for (int r = 0; r < 8; r++) {
        int n = n0 + ty * 8 + r;
        float4 v;
        unpack2(acc[r][0], v.x, v.y);
        unpack2(acc[r][1], v.z, v.w);
        // FIXED (round-5 bug): include the block's column offset j0 (via jj).
        *(float4*)&g_Z[(size_t)n * H_ + jj] = v;     // jj even -> 16B aligned
    }
}

// ---------------------------------------------------------------------------
// Recurrence: 32 blocks x 2 batches, 256 threads, thread = column j, both batches.
//   acc{f,c}[b][j] += sum_k h[b][k] * Wh[k][j]   via f32x2 (gates in lanes)
// First CK weight rows from smem, rest streamed from L2 (resident, all blocks share).
// h kept PRE-SPLATTED ({h,h}) in smem -> zero pack instructions in inner loop.
// ---------------------------------------------------------------------------
__global__ void __launch_bounds__(256, 1) mgu_recur(
    int layer, float* __restrict__ Yext, float* __restrict__ Hfin)
{
    extern __shared__ u64 sm[];
    u64* sW  = sm;                 // [CK * 256]
    u64* hs0 = sm + CK * H_;       // [256] splatted h, batch 0
    u64* hs1 = hs0 + H_;           // [256] splatted h, batch 1

    const int j  = threadIdx.x;
    const int b0 = blockIdx.x * 2;
    const int b1 = b0 + 1;

    const u64*    __restrict__ Whg = g_Wh[layer];
    const float2* __restrict__ Z   = g_Z;
    float*        __restrict__ Y   = (layer == 0) ? (float*)g_y1 : Yext;

    // cache first CK weight rows in smem (16B chunks)
    {
        const ulonglong2* src = (const ulonglong2*)Whg;
        ulonglong2*       dst = (ulonglong2*)sW;
        for (int i = j; i < CK * H_ / 2; i += 256) dst[i] = src[i];
    }
    hs0[j] = 0ULL;
    hs1[j] = 0ULL;
    __syncthreads();

    const size_t zb0 = (size_t)b0 * T_ * H_;
    const size_t zb1 = (size_t)b1 * T_ * H_;

    for (int t = 0; t < T_; t++) {
        // z loads issued up front; consumed only after the k-loop (latency hidden)
        float2 z0 = Z[zb0 + (size_t)t * H_ + j];
        float2 z1 = Z[zb1 + (size_t)t * H_ + j];

        u64 acc0 = 0ULL, acc1 = 0ULL;

#pragma unroll 4
        for (int k = 0; k < CK; k += 2) {
            ulonglong2 ha = *(const ulonglong2*)(hs0 + k);   // {h[k],h[k]},{h[k+1],h[k+1]}
            ulonglong2 hb = *(const ulonglong2*)(hs1 + k);
            u64 w0 = sW[k * H_ + j];
            u64 w1 = sW[(k + 1) * H_ + j];
            ffma2(acc0, ha.x, w0);
            ffma2(acc0, ha.y, w1);
            ffma2(acc1, hb.x, w0);
            ffma2(acc1, hb.y, w1);
        }
#pragma unroll 4
        for (int k = CK; k < H_; k += 2) {
            ulonglong2 ha = *(const ulonglong2*)(hs0 + k);
            ulonglong2 hb = *(const ulonglong2*)(hs1 + k);
            u64 w0 = Whg[k * H_ + j];
            u64 w1 = Whg[(k + 1) * H_ + j];
            ffma2(acc0, ha.x, w0);
            ffma2(acc0, ha.y, w1);
            ffma2(acc1, hb.x, w0);
            ffma2(acc1, hb.y, w1);
        }

        float a0f, a0c, a1f, a1c;
        unpack2(acc0, a0f, a0c);
        unpack2(acc1, a1f, a1c);
        a0f += z0.x; a0c += z0.y;
        a1f += z1.x; a1c += z1.y;

        float hold0, dead0, hold1, dead1;
        unpack2(hs0[j], hold0, dead0);
        unpack2(hs1[j], hold1, dead1);
        (void)dead0; (void)dead1;

        float f0 = 1.0f / (1.0f + expf(-a0f));
        float c0 = tanhf(a0c);
        float f1 = 1.0f / (1.0f + expf(-a1f));
        float c1 = tanhf(a1c);
        float hn0 = fmaf(f0, hold0 - c0, c0);   // f*h + (1-f)*c
        float hn1 = fmaf(f1, hold1 - c1, c1);

        __syncthreads();                         // all k-loop reads done
        hs0[j] = pack2(hn0, hn0);
        hs1[j] = pack2(hn1, hn1);
        Y[zb0 + (size_t)t * H_ + j] = hn0;
        Y[zb1 + (size_t)t * H_ + j] = hn1;
        if (t == T_ - 1) {
            Hfin[b0 * H_ + j] = hn0;
            Hfin[b1 * H_ + j] = hn1;
        }
        __syncthreads();                         // new h visible before next step
    }
}

// ---------------------------------------------------------------------------
// Launch
// ---------------------------------------------------------------------------
extern "C" void kernel_launch(void* const* d_in, const int* in_sizes, int n_in,
                              void* d_out, int out_size)
{
    const float* x   = (const float*)d_in[0];
    const float* Wf1 = (const float*)d_in[1];
    const float* bf1 = (const float*)d_in[2];
    const float* Wc1 = (const float*)d_in[3];
    const float* bc1 = (const float*)d_in[4];
    const float* Wf2 = (const float*)d_in[5];
    const float* bf2 = (const float*)d_in[6];
    const float* Wc2 = (const float*)d_in[7];
    const float* bc2 = (const float*)d_in[8];

    float* out = (float*)d_out;
    float* y2  = out;                               // [B, T, H]
    float* h1  = out + (size_t)NT * H_;             // hidden[0]
    float* h2  = h1 + (size_t)B_ * H_;              // hidden[1]

    const int recur_smem = (CK * H_ + 2 * H_) * (int)sizeof(u64);  // 217088 B
    cudaFuncSetAttribute(mgu_recur, cudaFuncAttributeMaxDynamicSharedMemorySize,
                         recur_smem);

    // weight repack (both layers)
    repack_wh<<<H_, H_>>>(Wf1, Wc1, I_, 0);
    repack_wh<<<H_, H_>>>(Wf2, Wc2, H_, 1);

    // layer 1
    gemm_x<<<dim3(NT / 128, H_ / 32), 256>>>(x, I_, 0, Wf1, Wc1, bf1, bc1);
    mgu_recur<<<B_ / 2, H_, recur_smem>>>(0, nullptr, h1);

    // layer 2 (reads g_y1)
    gemm_x<<<dim3(NT / 128, H_ / 32), 256>>>(nullptr, H_, 1, Wf2, Wc2, bf2, bc2);
    mgu_recur<<<B_ / 2, H_, recur_smem>>>(1, y2, h2);
}

// round 7
// speedup vs baseline: 4.3980x; 4.3980x over previous
#include <cuda_runtime.h>
#include <cuda_bf16.h>
#include <cstdint>
#include <math.h>

// Problem constants
#define B_  64
#define T_  1024
#define I_  128
#define H_  256
#define NT  (B_ * T_)          // 65536 rows

typedef unsigned long long u64;

// ---------------------------------------------------------------------------
// Static device scratch (no runtime allocation allowed)
// ---------------------------------------------------------------------------
__device__ float2 g_Z[(size_t)NT * H_];        // {zf, zc} x-part (+bias), 128 MB
__device__ float  g_y1[(size_t)NT * H_];       // layer-1 outputs, 64 MB
__device__ u64    g_Wh[2][H_ * H_];            // recurrent weights {wf,wc} packed, k-major

// ---------------------------------------------------------------------------
// f32x2 + PTX helpers
// ---------------------------------------------------------------------------
__device__ __forceinline__ u64 pack2(float x, float y) {
    u64 r;
    asm("mov.b64 %0, {%1, %2};" : "=l"(r) : "f"(x), "f"(y));
    return r;
}
__device__ __forceinline__ void unpack2(u64 v, float& x, float& y) {
    asm("mov.b64 {%0, %1}, %2;" : "=f"(x), "=f"(y) : "l"(v));
}
__device__ __forceinline__ void ffma2(u64& d, u64 a, u64 b) {
    asm("fma.rn.f32x2 %0, %1, %2, %0;" : "+l"(d) : "l"(a), "l"(b));
}
__device__ __forceinline__ u64 fadd2(u64 a, u64 b) {
    u64 d;
    asm("add.rn.f32x2 %0, %1, %2;" : "=l"(d) : "l"(a), "l"(b));
    return d;
}
__device__ __forceinline__ uint32_t smem_u32(const void* p) {
    uint32_t a;
    asm("{ .reg .u64 t; cvta.to.shared.u64 t, %1; cvt.u32.u64 %0, t; }"
        : "=r"(a) : "l"(p));
    return a;
}
__device__ __forceinline__ uint32_t cluster_rank() {
    uint32_t r;
    asm("mov.u32 %0, %%cluster_ctarank;" : "=r"(r));
    return r;
}
__device__ __forceinline__ uint32_t mapa_u32(uint32_t addr, uint32_t rank) {
    uint32_t r;
    asm("mapa.shared::cluster.u32 %0, %1, %2;" : "=r"(r) : "r"(addr), "r"(rank));
    return r;
}
__device__ __forceinline__ void st_cluster_u64(uint32_t addr, u64 v) {
    asm volatile("st.shared::cluster.u64 [%0], %1;" :: "r"(addr), "l"(v) : "memory");
}
__device__ __forceinline__ void cluster_arrive() {
    asm volatile("barrier.cluster.arrive.aligned;" ::: "memory");
}
__device__ __forceinline__ void cluster_wait() {
    asm volatile("barrier.cluster.wait.aligned;" ::: "memory");
}

// ---------------------------------------------------------------------------
// Repack recurrent weight rows: g_Wh[layer][k*H + j] = pack{Wf[D+k][j], Wc[D+k][j]}
// ---------------------------------------------------------------------------
__global__ void repack_wh(const float* __restrict__ Wf, const float* __restrict__ Wc,
                          int D, int layer)
{
    int j = threadIdx.x;
    int k = blockIdx.x;
    float wf = Wf[(size_t)(D + k) * H_ + j];
    float wc = Wc[(size_t)(D + k) * H_ + j];
    g_Wh[layer][k * H_ + j] = pack2(wf, wc);
}

// ---------------------------------------------------------------------------
// Precompute x-part of both gates (unchanged from passing round 6):
//   g_Z[n][j] = { bf[j] + sum_d X[n][d]*Wf[d][j],  bc[j] + sum_d X[n][d]*Wc[d][j] }
// ---------------------------------------------------------------------------
__global__ void __launch_bounds__(256) gemm_x(
    const float* __restrict__ Xext, int D, int useY1,
    const float* __restrict__ Wf, const float* __restrict__ Wc,
    const float* __restrict__ bf, const float* __restrict__ bc)
{
    const float* __restrict__ X = useY1 ? (const float*)g_y1 : Xext;

    __shared__ float2 Xs[16][130];   // x splatted {x,x}
    __shared__ float2 Ws[16][34];    // {wf,wc}

    const int tid = threadIdx.x;
    const int tx  = tid & 15;
    const int ty  = tid >> 4;
    const int n0  = blockIdx.x * 128;
    const int j0  = blockIdx.y * 32;
    const int jj  = j0 + 2 * tx;

    u64 acc[8][2];
    {
        u64 bi0 = pack2(bf[jj],     bc[jj]);
        u64 bi1 = pack2(bf[jj + 1], bc[jj + 1]);
#pragma unroll
        for (int r = 0; r < 8; r++) { acc[r][0] = bi0; acc[r][1] = bi1; }
    }

    for (int d0 = 0; d0 < D; d0 += 16) {
        __syncthreads();
        {
            int r  = tid >> 2;
            int c4 = (tid & 3) * 4;
#pragma unroll
            for (int rr = 0; rr < 2; rr++) {
                int row = r + rr * 64;
                float4 v = *(const float4*)&X[(size_t)(n0 + row) * D + d0 + c4];
                Xs[c4 + 0][row] = make_float2(v.x, v.x);
                Xs[c4 + 1][row] = make_float2(v.y, v.y);
                Xs[c4 + 2][row] = make_float2(v.z, v.z);
                Xs[c4 + 3][row] = make_float2(v.w, v.w);
            }
        }
        for (int e = tid; e < 512; e += 256) {
            int k = e >> 5, jw = e & 31;
            Ws[k][jw] = make_float2(Wf[(size_t)(d0 + k) * H_ + j0 + jw],
                                    Wc[(size_t)(d0 + k) * H_ + j0 + jw]);
        }
        __syncthreads();

#pragma unroll
        for (int kk = 0; kk < 16; kk++) {
            ulonglong2 wq = *(const ulonglong2*)&Ws[kk][2 * tx];
            const ulonglong2* xp = (const ulonglong2*)&Xs[kk][ty * 8];
#pragma unroll
            for (int q = 0; q < 4; q++) {
                ulonglong2 xq = xp[q];
                ffma2(acc[2 * q + 0][0], xq.x, wq.x);
                ffma2(acc[2 * q + 0][1], xq.x, wq.y);
                ffma2(acc[2 * q + 1][0], xq.y, wq.x);
                ffma2(acc[2 * q + 1][1], xq.y, wq.y);
            }
        }
    }

#pragma unroll
    for (int r = 0; r < 8; r++) {
        int n = n0 + ty * 8 + r;
        float4 v;
        unpack2(acc[r][0], v.x, v.y);
        unpack2(acc[r][1], v.z, v.w);
        *(float4*)&g_Z[(size_t)n * H_ + jj] = v;
    }
}

// ---------------------------------------------------------------------------
// Recurrence v2: cluster of 4 CTAs, CTA = 64 columns x full K, 2 batches/cluster.
// ALL recurrent weights in smem (zero LDG in loop). 128 threads: thread =
// (column jl, k-half kh), serves both batches in registers.
// h exchanged via DSMEM stores into parity-double-buffered arrays; one
// cluster barrier per step.
// ---------------------------------------------------------------------------
#define SW_U64   (128 * 128)     // 128 k-pairs x 64 cols x {even,odd} = 16384 u64
#define HBUF_U64 (2 * 2 * 256)   // [parity][batch][k] splatted h
#define RED_U64  (2 * 64)        // k-half reduction: [batch][jl]
#define RSMEM_B  ((SW_U64 + HBUF_U64 + RED_U64) * 8)   // 140288 bytes

__global__ void __cluster_dims__(4, 1, 1) __launch_bounds__(128, 1)
mgu_recur2(int layer, float* __restrict__ Yext, float* __restrict__ Hfin)
{
    extern __shared__ u64 sm[];
    u64* sW   = sm;                        // [kp*128 + jl*2 + {0,1}]
    u64* hbuf = sm + SW_U64;               // [(p*2+b)*256 + k]
    u64* red  = sm + SW_U64 + HBUF_U64;    // [b*64 + jl]

    const int tid = threadIdx.x;
    const int jl  = tid & 63;              // local column
    const int kh  = tid >> 6;              // k-half 0/1
    const uint32_t rank = cluster_rank();  // 0..3 -> column block
    const int c   = blockIdx.x >> 2;       // cluster id -> batch pair
    const int b0  = 2 * c, b1 = 2 * c + 1;
    const int jg  = (int)rank * 64 + jl;   // global column

    const u64* __restrict__ Whg = g_Wh[layer];
    float* __restrict__ Y = (layer == 0) ? (float*)g_y1 : Yext;

    // Load this CTA's weight slice: pairs (k even, k odd) adjacent per column.
    for (int m = tid; m < 128 * 64; m += 128) {
        int kp = m >> 6, j2 = m & 63;
        ulonglong2 wv;
        wv.x = Whg[(size_t)(2 * kp)     * H_ + rank * 64 + j2];
        wv.y = Whg[(size_t)(2 * kp + 1) * H_ + rank * 64 + j2];
        *(ulonglong2*)(sW + kp * 128 + j2 * 2) = wv;
    }
    // zero parity-0 h buffers (both batches)
    for (int m = tid; m < 512; m += 128) hbuf[m] = 0ULL;
    __syncthreads();
    cluster_arrive();
    cluster_wait();

    const uint32_t smem_base = smem_u32(sm);
    uint32_t peer[4];
#pragma unroll
    for (int r = 0; r < 4; r++) peer[r] = mapa_u32(smem_base, (uint32_t)r);

    const size_t zb0 = (size_t)b0 * T_ * H_;
    const size_t zb1 = (size_t)b1 * T_ * H_;

    for (int t = 0; t < T_; t++) {
        const int p = t & 1, q = p ^ 1;
        const u64* __restrict__ hb0 = hbuf + (p * 2 + 0) * 256;
        const u64* __restrict__ hb1 = hbuf + (p * 2 + 1) * 256;

        float2 z0 = make_float2(0.f, 0.f), z1 = make_float2(0.f, 0.f);
        if (kh == 0) {
            z0 = g_Z[zb0 + (size_t)t * H_ + jg];   // DRAM/L2; consumed after k-loop
            z1 = g_Z[zb1 + (size_t)t * H_ + jg];
        }

        u64 a0e = 0, a0o = 0, a1e = 0, a1o = 0;
        const int kp0 = kh * 64;
#pragma unroll 16
        for (int kp = kp0; kp < kp0 + 64; kp++) {
            ulonglong2 ha  = *(const ulonglong2*)(hb0 + 2 * kp);      // bcast
            ulonglong2 hbv = *(const ulonglong2*)(hb1 + 2 * kp);      // bcast
            ulonglong2 w   = *(const ulonglong2*)(sW + kp * 128 + jl * 2);
            ffma2(a0e, ha.x,  w.x);
            ffma2(a0o, ha.y,  w.y);
            ffma2(a1e, hbv.x, w.x);
            ffma2(a1o, hbv.y, w.y);
        }
        u64 s0 = fadd2(a0e, a0o);
        u64 s1 = fadd2(a1e, a1o);
        if (kh == 1) { red[jl] = s0; red[64 + jl] = s1; }
        __syncthreads();

        if (kh == 0) {
            s0 = fadd2(s0, red[jl]);
            s1 = fadd2(s1, red[64 + jl]);
            float af0, ac0, af1, ac1;
            unpack2(s0, af0, ac0);
            unpack2(s1, af1, ac1);
            af0 += z0.x; ac0 += z0.y;
            af1 += z1.x; ac1 += z1.y;

            float h0o, h1o, dm;
            unpack2(hb0[jg], h0o, dm);
            unpack2(hb1[jg], h1o, dm);

            float f0 = 1.0f / (1.0f + __expf(-af0));
            float c0 = 1.0f - 2.0f / (__expf(2.0f * ac0) + 1.0f);   // tanh
            float f1 = 1.0f / (1.0f + __expf(-af1));
            float c1 = 1.0f - 2.0f / (__expf(2.0f * ac1) + 1.0f);
            float hn0 = fmaf(f0, h0o - c0, c0);   // f*h + (1-f)*c
            float hn1 = fmaf(f1, h1o - c1, c1);

            u64 pk0 = pack2(hn0, hn0);
            u64 pk1 = pack2(hn1, hn1);
            uint32_t off0 = (uint32_t)((SW_U64 + (q * 2 + 0) * 256 + jg) * 8);
            uint32_t off1 = (uint32_t)((SW_U64 + (q * 2 + 1) * 256 + jg) * 8);
#pragma unroll
            for (int r = 0; r < 4; r++) {
                st_cluster_u64(peer[r] + off0, pk0);   // includes self
                st_cluster_u64(peer[r] + off1, pk1);
            }
            Y[zb0 + (size_t)t * H_ + jg] = hn0;
            Y[zb1 + (size_t)t * H_ + jg] = hn1;
            if (t == T_ - 1) {
                Hfin[b0 * H_ + jg] = hn0;
                Hfin[b1 * H_ + jg] = hn1;
            }
        }
        cluster_arrive();   // release: orders DSMEM h stores cluster-wide
        cluster_wait();     // acquire: peers' h for parity q now visible
    }
}

// ---------------------------------------------------------------------------
// Launch
// ---------------------------------------------------------------------------
extern "C" void kernel_launch(void* const* d_in, const int* in_sizes, int n_in,
                              void* d_out, int out_size)
{
    const float* x   = (const float*)d_in[0];
    const float* Wf1 = (const float*)d_in[1];
    const float* bf1 = (const float*)d_in[2];
    const float* Wc1 = (const float*)d_in[3];
    const float* bc1 = (const float*)d_in[4];
    const float* Wf2 = (const float*)d_in[5];
    const float* bf2 = (const float*)d_in[6];
    const float* Wc2 = (const float*)d_in[7];
    const float* bc2 = (const float*)d_in[8];

    float* out = (float*)d_out;
    float* y2  = out;                               // [B, T, H]
    float* h1  = out + (size_t)NT * H_;             // hidden[0]
    float* h2  = h1 + (size_t)B_ * H_;              // hidden[1]

    cudaFuncSetAttribute(mgu_recur2, cudaFuncAttributeMaxDynamicSharedMemorySize,
                         RSMEM_B);

    // weight repack (both layers)
    repack_wh<<<H_, H_>>>(Wf1, Wc1, I_, 0);
    repack_wh<<<H_, H_>>>(Wf2, Wc2, H_, 1);

    // layer 1
    gemm_x<<<dim3(NT / 128, H_ / 32), 256>>>(x, I_, 0, Wf1, Wc1, bf1, bc1);
    mgu_recur2<<<128, 128, RSMEM_B>>>(0, nullptr, h1);

    // layer 2 (reads g_y1)
    gemm_x<<<dim3(NT / 128, H_ / 32), 256>>>(nullptr, H_, 1, Wf2, Wc2, bf2, bc2);
    mgu_recur2<<<128, 128, RSMEM_B>>>(1, y2, h2);
}

// round 9
// speedup vs baseline: 5.9678x; 1.3570x over previous
#include <cuda_runtime.h>
#include <cuda_bf16.h>
#include <cstdint>
#include <math.h>

// Problem constants
#define B_  64
#define T_  1024
#define I_  128
#define H_  256
#define NT  (B_ * T_)          // 65536 rows

typedef unsigned long long u64;

// ---------------------------------------------------------------------------
// Static device scratch (no runtime allocation allowed)
// ---------------------------------------------------------------------------
__device__ float2 g_Z[(size_t)NT * H_];        // {zf, zc} x-part (+bias), 128 MB
__device__ float  g_y1[(size_t)NT * H_];       // layer-1 outputs, 64 MB
__device__ u64    g_Wh[2][H_ * H_];            // recurrent weights {wf,wc} packed, k-major

// ---------------------------------------------------------------------------
// f32x2 + PTX helpers
// ---------------------------------------------------------------------------
__device__ __forceinline__ u64 pack2(float x, float y) {
    u64 r;
    asm("mov.b64 %0, {%1, %2};" : "=l"(r) : "f"(x), "f"(y));
    return r;
}
__device__ __forceinline__ void unpack2(u64 v, float& x, float& y) {
    asm("mov.b64 {%0, %1}, %2;" : "=f"(x), "=f"(y) : "l"(v));
}
__device__ __forceinline__ void ffma2(u64& d, u64 a, u64 b) {
    asm("fma.rn.f32x2 %0, %1, %2, %0;" : "+l"(d) : "l"(a), "l"(b));
}
__device__ __forceinline__ u64 fadd2(u64 a, u64 b) {
    u64 d;
    asm("add.rn.f32x2 %0, %1, %2;" : "=l"(d) : "l"(a), "l"(b));
    return d;
}
__device__ __forceinline__ uint32_t smem_u32(const void* p) {
    uint32_t a;
    asm("{ .reg .u64 t; cvta.to.shared.u64 t, %1; cvt.u32.u64 %0, t; }"
        : "=r"(a) : "l"(p));
    return a;
}
__device__ __forceinline__ uint32_t cluster_rank() {
    uint32_t r;
    asm("mov.u32 %0, %%cluster_ctarank;" : "=r"(r));
    return r;
}
__device__ __forceinline__ uint32_t mapa_u32(uint32_t addr, uint32_t rank) {
    uint32_t r;
    asm("mapa.shared::cluster.u32 %0, %1, %2;" : "=r"(r) : "r"(addr), "r"(rank));
    return r;
}
__device__ __forceinline__ void st_cluster_u64(uint32_t addr, u64 v) {
    asm volatile("st.shared::cluster.u64 [%0], %1;" :: "r"(addr), "l"(v) : "memory");
}
__device__ __forceinline__ void cluster_arrive() {
    asm volatile("barrier.cluster.arrive.aligned;" ::: "memory");
}
__device__ __forceinline__ void cluster_wait() {
    asm volatile("barrier.cluster.wait.aligned;" ::: "memory");
}

// ---------------------------------------------------------------------------
// Repack recurrent weight rows: g_Wh[layer][k*H + j] = pack{Wf[D+k][j], Wc[D+k][j]}
// ---------------------------------------------------------------------------
__global__ void repack_wh(const float* __restrict__ Wf, const float* __restrict__ Wc,
                          int D, int layer)
{
    int j = threadIdx.x;
    int k = blockIdx.x;
    float wf = Wf[(size_t)(D + k) * H_ + j];
    float wc = Wc[(size_t)(D + k) * H_ + j];
    g_Wh[layer][k * H_ + j] = pack2(wf, wc);
}

// ---------------------------------------------------------------------------
// Precompute x-part of both gates (unchanged, passing since round 6):
//   g_Z[n][j] = { bf[j] + sum_d X[n][d]*Wf[d][j],  bc[j] + sum_d X[n][d]*Wc[d][j] }
// ---------------------------------------------------------------------------
__global__ void __launch_bounds__(256) gemm_x(
    const float* __restrict__ Xext, int D, int useY1,
    const float* __restrict__ Wf, const float* __restrict__ Wc,
    const float* __restrict__ bf, const float* __restrict__ bc)
{
    const float* __restrict__ X = useY1 ? (const float*)g_y1 : Xext;

    __shared__ float2 Xs[16][130];   // x splatted {x,x}
    __shared__ float2 Ws[16][34];    // {wf,wc}

    const int tid = threadIdx.x;
    const int tx  = tid & 15;
    const int ty  = tid >> 4;
    const int n0  = blockIdx.x * 128;
    const int j0  = blockIdx.y * 32;
    const int jj  = j0 + 2 * tx;

    u64 acc[8][2];
    {
        u64 bi0 = pack2(bf[jj],     bc[jj]);
        u64 bi1 = pack2(bf[jj + 1], bc[jj + 1]);
#pragma unroll
        for (int r = 0; r < 8; r++) { acc[r][0] = bi0; acc[r][1] = bi1; }
    }

    for (int d0 = 0; d0 < D; d0 += 16) {
        __syncthreads();
        {
            int r  = tid >> 2;
            int c4 = (tid & 3) * 4;
#pragma unroll
            for (int rr = 0; rr < 2; rr++) {
                int row = r + rr * 64;
                float4 v = *(const float4*)&X[(size_t)(n0 + row) * D + d0 + c4];
                Xs[c4 + 0][row] = make_float2(v.x, v.x);
                Xs[c4 + 1][row] = make_float2(v.y, v.y);
                Xs[c4 + 2][row] = make_float2(v.z, v.z);
                Xs[c4 + 3][row] = make_float2(v.w, v.w);
            }
        }
        for (int e = tid; e < 512; e += 256) {
            int k = e >> 5, jw = e & 31;
            Ws[k][jw] = make_float2(Wf[(size_t)(d0 + k) * H_ + j0 + jw],
                                    Wc[(size_t)(d0 + k) * H_ + j0 + jw]);
        }
        __syncthreads();

#pragma unroll
        for (int kk = 0; kk < 16; kk++) {
            ulonglong2 wq = *(const ulonglong2*)&Ws[kk][2 * tx];
            const ulonglong2* xp = (const ulonglong2*)&Xs[kk][ty * 8];
#pragma unroll
            for (int q = 0; q < 4; q++) {
                ulonglong2 xq = xp[q];
                ffma2(acc[2 * q + 0][0], xq.x, wq.x);
                ffma2(acc[2 * q + 0][1], xq.x, wq.y);
                ffma2(acc[2 * q + 1][0], xq.y, wq.x);
                ffma2(acc[2 * q + 1][1], xq.y, wq.y);
            }
        }
    }

#pragma unroll
    for (int r = 0; r < 8; r++) {
        int n = n0 + ty * 8 + r;
        float4 v;
        unpack2(acc[r][0], v.x, v.y);
        unpack2(acc[r][1], v.z, v.w);
        *(float4*)&g_Z[(size_t)n * H_ + jj] = v;
    }
}

// ---------------------------------------------------------------------------
// Recurrence v3: cluster of 4 CTAs, CTA = 64 columns x full K, 2 batches.
// REGISTER-RESIDENT WEIGHTS: 256 threads, thread = (col jl, K-quarter kq),
// holds its 32 k-pairs (64 u64) in registers for all 1024 steps.
// Zero weight memory traffic in the loop; only broadcast h-reads from smem.
// h exchanged via DSMEM stores into parity-double-buffered arrays; cluster
// barrier per step with early-arrive / late-wait (Y stores + z prefetch
// overlap the barrier).
// ---------------------------------------------------------------------------
__global__ void __cluster_dims__(4, 1, 1) __launch_bounds__(256, 1)
mgu_recur3(int layer, float* __restrict__ Yext, float* __restrict__ Hfin)
{
    __shared__ __align__(16) u64 hbuf[2][2][256];   // [parity][batch][k] splatted {h,h}
    __shared__ __align__(16) u64 red[3][2][64];     // partial sums from kq=1..3

    const int tid = threadIdx.x;
    const int jl  = tid & 63;              // local column
    const int kq  = tid >> 6;              // K-quarter 0..3
    const uint32_t rank = cluster_rank();  // 0..3 -> column block
    const int c   = blockIdx.x >> 2;       // cluster id -> batch pair
    const int b0  = 2 * c, b1 = 2 * c + 1;
    const int jg  = (int)rank * 64 + jl;   // global column

    const u64* __restrict__ Whg = g_Wh[layer];
    float* __restrict__ Y = (layer == 0) ? (float*)g_y1 : Yext;

    // Load this thread's 32 weight k-pairs into registers (step-invariant).
    u64 wreg[64];
#pragma unroll
    for (int i = 0; i < 32; i++) {
        int k = 2 * (kq * 32 + i);
        wreg[2 * i]     = Whg[(size_t)k * H_ + jg];
        wreg[2 * i + 1] = Whg[(size_t)(k + 1) * H_ + jg];
    }

    // zero parity-0 h buffers ONLY (parity-1 is written by peers at step 0)
    for (int m = tid; m < 512; m += 256) (&hbuf[0][0][0])[m] = 0ULL;
    __syncthreads();
    cluster_arrive();   // no peer may start step 0 before all init done
    cluster_wait();

    const uint32_t hb_addr = smem_u32(&hbuf[0][0][0]);
    uint32_t peer[4];
#pragma unroll
    for (int r = 0; r < 4; r++) peer[r] = mapa_u32(hb_addr, (uint32_t)r);

    const size_t zb0 = (size_t)b0 * T_ * H_;
    const size_t zb1 = (size_t)b1 * T_ * H_;

    float2 z0 = make_float2(0.f, 0.f), z1 = make_float2(0.f, 0.f);
    if (kq == 0) {                         // prefetch z for t=0
        z0 = g_Z[zb0 + jg];
        z1 = g_Z[zb1 + jg];
    }

    for (int t = 0; t < T_; t++) {
        const int p = t & 1, q = p ^ 1;
        const u64* __restrict__ hbp0 = &hbuf[p][0][0];
        const u64* __restrict__ hbp1 = &hbuf[p][1][0];

        u64 a0e = 0, a0o = 0, a1e = 0, a1o = 0;
#pragma unroll
        for (int i = 0; i < 32; i++) {
            int kp = kq * 32 + i;
            ulonglong2 ha = *(const ulonglong2*)(hbp0 + 2 * kp);  // broadcast
            ulonglong2 hb = *(const ulonglong2*)(hbp1 + 2 * kp);  // broadcast
            ffma2(a0e, ha.x, wreg[2 * i]);
            ffma2(a0o, ha.y, wreg[2 * i + 1]);
            ffma2(a1e, hb.x, wreg[2 * i]);
            ffma2(a1o, hb.y, wreg[2 * i + 1]);
        }
        u64 s0 = fadd2(a0e, a0o);
        u64 s1 = fadd2(a1e, a1o);
        if (kq) { red[kq - 1][0][jl] = s0; red[kq - 1][1][jl] = s1; }
        __syncthreads();

        float hn0 = 0.f, hn1 = 0.f;
        if (kq == 0) {
            s0 = fadd2(fadd2(s0, red[0][0][jl]), fadd2(red[1][0][jl], red[2][0][jl]));
            s1 = fadd2(fadd2(s1, red[0][1][jl]), fadd2(red[1][1][jl], red[2][1][jl]));
            float af0, ac0, af1, ac1;
            unpack2(s0, af0, ac0);
            unpack2(s1, af1, ac1);
            af0 += z0.x; ac0 += z0.y;
            af1 += z1.x; ac1 += z1.y;

            float h0o, h1o, dm;
            unpack2(hbp0[jg], h0o, dm);
            unpack2(hbp1[jg], h1o, dm);

            float f0 = 1.0f / (1.0f + __expf(-af0));
            float c0 = 1.0f - 2.0f / (__expf(2.0f * ac0) + 1.0f);   // tanh
            float f1 = 1.0f / (1.0f + __expf(-af1));
            float c1 = 1.0f - 2.0f / (__expf(2.0f * ac1) + 1.0f);
            hn0 = fmaf(f0, h0o - c0, c0);   // f*h + (1-f)*c
            hn1 = fmaf(f1, h1o - c1, c1);

            u64 pk0 = pack2(hn0, hn0);
            u64 pk1 = pack2(hn1, hn1);
            uint32_t off0 = (uint32_t)(((q * 2 + 0) * 256 + jg) * 8);
            uint32_t off1 = (uint32_t)(((q * 2 + 1) * 256 + jg) * 8);
#pragma unroll
            for (int r = 0; r < 4; r++) {
                st_cluster_u64(peer[r] + off0, pk0);   // includes self
                st_cluster_u64(peer[r] + off1, pk1);
            }
        }
        cluster_arrive();   // release: DSMEM h stores ordered cluster-wide

        // overlap the barrier with global traffic
        if (kq == 0) {
            Y[zb0 + (size_t)t * H_ + jg] = hn0;
            Y[zb1 + (size_t)t * H_ + jg] = hn1;
            if (t == T_ - 1) {
                Hfin[b0 * H_ + jg] = hn0;
                Hfin[b1 * H_ + jg] = hn1;
            } else {
                z0 = g_Z[zb0 + (size_t)(t + 1) * H_ + jg];
                z1 = g_Z[zb1 + (size_t)(t + 1) * H_ + jg];
            }
        }
        cluster_wait();     // acquire: peers' h for parity q now visible
    }
}

// ---------------------------------------------------------------------------
// Launch
// ---------------------------------------------------------------------------
extern "C" void kernel_launch(void* const* d_in, const int* in_sizes, int n_in,
                              void* d_out, int out_size)
{
    const float* x   = (const float*)d_in[0];
    const float* Wf1 = (const float*)d_in[1];
    const float* bf1 = (const float*)d_in[2];
    const float* Wc1 = (const float*)d_in[3];
    const float* bc1 = (const float*)d_in[4];
    const float* Wf2 = (const float*)d_in[5];
    const float* bf2 = (const float*)d_in[6];
    const float* Wc2 = (const float*)d_in[7];
    const float* bc2 = (const float*)d_in[8];

    float* out = (float*)d_out;
    float* y2  = out;                               // [B, T, H]
    float* h1  = out + (size_t)NT * H_;             // hidden[0]
    float* h2  = h1 + (size_t)B_ * H_;              // hidden[1]

    // weight repack (both layers)
    repack_wh<<<H_, H_>>>(Wf1, Wc1, I_, 0);
    repack_wh<<<H_, H_>>>(Wf2, Wc2, H_, 1);

    // layer 1
    gemm_x<<<dim3(NT / 128, H_ / 32), 256>>>(x, I_, 0, Wf1, Wc1, bf1, bc1);
    mgu_recur3<<<128, 256>>>(0, nullptr, h1);

    // layer 2 (reads g_y1)
    gemm_x<<<dim3(NT / 128, H_ / 32), 256>>>(nullptr, H_, 1, Wf2, Wc2, bf2, bc2);
    mgu_recur3<<<128, 256>>>(1, y2, h2);
}